// round 5
// baseline (speedup 1.0000x reference)
#include <cuda_runtime.h>

// EnhancedLesionPenaltyLoss: pred (16,1,128,128,128) fp32 -> scalar loss.
// Grid: 16 batches x 16 row-strips(8 rows) x 4 z-segments(32 slices)
//     = 1024 blocks x 256 threads, __launch_bounds__(256,7): whole grid
//     co-resident in one wave (148*7=1036 >= 1024).
// h/d gradient diffs via packed f32x2 (fma.rn.f32x2 / add.rn.f32x2) with
// abs on the ALU pipe (64-bit AND) to relieve the binding FMA pipe.
// Threshold counters kept as integers (ALU pipe, exact).
// Last block (atomic ticket) does the deterministic final reduction.

namespace {
constexpr int NB      = 16;
constexpr int STRIPS  = 16;
constexpr int ZSEGS   = 4;
constexpr int ZLEN    = 32;
constexpr int NBLK    = NB * STRIPS * ZSEGS;   // 1024
constexpr int THREADS = 256;
constexpr int PLANE4  = 4096;                  // float4 per z-plane
constexpr int NACC    = 6;                     // cmin,cmax,max,sds,s1,s2
}

__device__ float        g_part[NBLK * NACC];
__device__ unsigned int g_ticket = 0;

using ull = unsigned long long;

struct alignas(16) F4U {
    union { float4 f; ull u[2]; };
};

__device__ __forceinline__ ull padd2(ull a, ull b) {
    ull d;
    asm("add.rn.f32x2 %0, %1, %2;" : "=l"(d) : "l"(a), "l"(b));
    return d;
}
// a - b  (computed as b * (-1) + a)
__device__ __forceinline__ ull psub2(ull a, ull b) {
    const ull NEG1 = 0xBF800000BF800000ULL;
    ull d;
    asm("fma.rn.f32x2 %0, %1, %2, %3;" : "=l"(d) : "l"(b), "l"(NEG1), "l"(a));
    return d;
}
__device__ __forceinline__ ull pabs2(ull a) {
    return a & 0x7FFFFFFF7FFFFFFFULL;   // 2x LOP3 on ALU pipe
}
__device__ __forceinline__ float plo(ull a) {
    return __uint_as_float((unsigned)(a & 0xFFFFFFFFu));
}
__device__ __forceinline__ float phi(ull a) {
    return __uint_as_float((unsigned)(a >> 32));
}

__global__ __launch_bounds__(THREADS, 7)
void lesion_fused(const float* __restrict__ pred, float* __restrict__ out) {
    const int bid   = blockIdx.x;
    const int zseg  = bid & 3;
    const int strip = (bid >> 2) & 15;
    const int b     = bid >> 6;
    const int tid   = threadIdx.x;
    const int lane  = tid & 31;
    const int wid   = tid >> 5;

    const float4* __restrict__ p =
        reinterpret_cast<const float4*>(pred) + (long long)b * (PLANE4 * 128);
    const int  o    = strip * 256 + tid;   // float4 index within a plane
    const int  grow = o >> 5;              // global row (lane == col4)
    const bool do_h = (grow < 127);
    const int  z0   = zseg * ZLEN;

    int   ci = 0, ch = 0;                  // counts (exact, ALU pipe)
    float mx = 0.f, sw = 0.f, s1 = 0.f, s2 = 0.f;
    ull   g2 = 0;                          // packed pair accumulator (h+d)

    // Seed prev with plane z0-1 (z0==0: self-diff contributes 0).
    const int zp = (z0 > 0) ? (z0 - 1) : 0;
    F4U prev; prev.f = p[zp * PLANE4 + o];

    const float4* pv = p + (long long)z0 * PLANE4 + o;
    const float4* ph = pv + 32;

#pragma unroll 2
    for (int i = 0; i < ZLEN; ++i) {
        F4U v; v.f = pv[i * PLANE4];
        F4U h;
        if (do_h) h.f = ph[i * PLANE4];

        // w-direction (scalar FADDs, fma pipe)
        const float nx = __shfl_down_sync(0xffffffffu, v.f.x, 1);
        sw += fabsf(v.f.y - v.f.x) + fabsf(v.f.z - v.f.y) + fabsf(v.f.w - v.f.z);
        if (lane != 31) sw += fabsf(nx - v.f.w);

        // h-direction (packed f32x2)
        if (do_h) {
            g2 = padd2(g2, pabs2(psub2(h.u[0], v.u[0])));
            g2 = padd2(g2, pabs2(psub2(h.u[1], v.u[1])));
        }
        // d-direction (packed f32x2, prev slice in registers)
        g2 = padd2(g2, pabs2(psub2(v.u[0], prev.u[0])));
        g2 = padd2(g2, pabs2(psub2(v.u[1], prev.u[1])));
        prev = v;

        // thresholds
        {
            const float x0 = v.f.x, x1 = v.f.y, x2 = v.f.z, x3 = v.f.w;
            if (x0 > 0.01f) { ci++; s1 += x0; s2 = fmaf(x0, x0, s2); }
            if (x1 > 0.01f) { ci++; s1 += x1; s2 = fmaf(x1, x1, s2); }
            if (x2 > 0.01f) { ci++; s1 += x2; s2 = fmaf(x2, x2, s2); }
            if (x3 > 0.01f) { ci++; s1 += x3; s2 = fmaf(x3, x3, s2); }
            if (x0 > 0.5f) ch++;
            if (x1 > 0.5f) ch++;
            if (x2 > 0.5f) ch++;
            if (x3 > 0.5f) ch++;
            mx = fmaxf(mx, fmaxf(fmaxf(x0, x1), fmaxf(x2, x3)));
        }
    }

    const float sds = sw + plo(g2) + phi(g2);

    // ---- block reduction (8 warps) ----
    float acc[NACC] = {(float)ci, (float)ch, mx, sds, s1, s2};
#pragma unroll
    for (int k = 0; k < NACC; ++k) {
#pragma unroll
        for (int off = 16; off; off >>= 1) {
            const float t = __shfl_xor_sync(0xffffffffu, acc[k], off);
            acc[k] = (k == 2) ? fmaxf(acc[k], t) : (acc[k] + t);
        }
    }
    __shared__ float red[8][NACC];
    __shared__ float fin[NB][NACC];
    __shared__ float lsh[NB];
    __shared__ unsigned int tick_sh;
    if (lane == 0) {
#pragma unroll
        for (int k = 0; k < NACC; ++k) red[wid][k] = acc[k];
    }
    __syncthreads();

    if (tid == 0) {
#pragma unroll
        for (int k = 0; k < NACC; ++k) {
            float r = red[0][k];
#pragma unroll
            for (int w = 1; w < 8; ++w)
                r = (k == 2) ? fmaxf(r, red[w][k]) : (r + red[w][k]);
            g_part[bid * NACC + k] = r;
        }
        __threadfence();
        tick_sh = atomicAdd(&g_ticket, 1u);
    }
    __syncthreads();
    if (tick_sh != (unsigned)(NBLK - 1)) return;

    // ---- last block: deterministic fixed-order final reduction ----
    __threadfence();  // acquire other blocks' g_part writes

    constexpr int PER_B = STRIPS * ZSEGS;  // 64 partials per batch
    if (tid < NB * NACC) {
        const int fb = tid / NACC;
        const int fk = tid % NACC;
        const float* base = &g_part[(fb * PER_B) * NACC + fk];
        float r = base[0];
#pragma unroll
        for (int c = 1; c < PER_B; ++c) {
            const float t = base[c * NACC];
            r = (fk == 2) ? fmaxf(r, t) : (r + t);
        }
        fin[fb][fk] = r;
    }
    __syncthreads();

    if (tid < NB) {
        const float cnt   = fin[tid][0];
        const float chigh = fin[tid][1];
        const float mxv   = fin[tid][2];
        const float sg    = fin[tid][3];
        const float S1    = fin[tid][4];
        const float S2    = fin[tid][5];

        const float invN   = 1.f / 2097152.f;        // 1/128^3
        const float invND3 = 1.f / 6242304.f;        // 1/(3*127*128*128)

        const float act = cnt * invN;
        float loss = fmaxf(0.005f - act, 0.f) * 15.f;

        const float high = chigh * invN;
        loss += fmaxf(high - 0.03f, 0.f) * 5.f;

        const float avg_grad = sg * invND3;
        if (mxv > 0.3f) loss += fminf(avg_grad, 1.f) * 5.f;

        const float cnt_safe = fmaxf(cnt, 1.f);
        const float m  = S1 / cnt_safe;
        const float sq = fmaxf(S2 - 2.f * m * S1 + m * m * cnt, 0.f);
        const bool gate = (act > 0.001f) && (cnt > 1.f);
        const float var = gate ? (sq / fmaxf(cnt - 1.f, 1.f)) : 1.f;
        const float rel_std = sqrtf(var) / (m + 1e-6f);
        const float pen = expf(-5.f * rel_std);
        loss += (gate ? pen : 0.f) * 7.f;

        lsh[tid] = loss;
    }
    __syncthreads();
    if (tid == 0) {
        float t = 0.f;
#pragma unroll
        for (int i = 0; i < NB; ++i) t += lsh[i];
        out[0] = t * (1.f / 16.f);
        g_ticket = 0;  // reset for next (graph-replayed) launch
    }
}

extern "C" void kernel_launch(void* const* d_in, const int* in_sizes, int n_in,
                              void* d_out, int out_size) {
    (void)in_sizes; (void)n_in; (void)out_size;
    const float* pred = (const float*)d_in[0];
    float* out = (float*)d_out;
    lesion_fused<<<NBLK, THREADS>>>(pred, out);
}

// round 6
// speedup vs baseline: 1.0727x; 1.0727x over previous
#include <cuda_runtime.h>

// EnhancedLesionPenaltyLoss: pred (16,1,128,128,128) fp32 -> scalar loss.
// Grid: 16 batches x 16 row-strips(8 rows) x 4 z-segments(32 slices)
//     = 1024 blocks x 256 threads, __launch_bounds__(256,7): whole grid
//     co-resident in one wave (148*7=1036 >= 1024). Unroll-4 z loop.
// Threshold tests use INTEGER compares (valid: inputs are non-negative),
// moving FSETP + count-FADD work off the binding fma pipe onto alu.
// Last block (atomic ticket) does the deterministic final reduction.

namespace {
constexpr int NB      = 16;
constexpr int STRIPS  = 16;
constexpr int ZSEGS   = 4;
constexpr int ZLEN    = 32;
constexpr int NBLK    = NB * STRIPS * ZSEGS;   // 1024
constexpr int THREADS = 256;
constexpr int PLANE4  = 4096;                  // float4 per z-plane
constexpr int NACC    = 6;                     // cmin,cmax,max,sds,s1,s2
constexpr unsigned U01 = 0x3C23D70Au;          // bits of 0.01f
constexpr unsigned U05 = 0x3F000000u;          // bits of 0.5f
}

__device__ float        g_part[NBLK * NACC];
__device__ unsigned int g_ticket = 0;

__global__ __launch_bounds__(THREADS, 7)
void lesion_fused(const float* __restrict__ pred, float* __restrict__ out) {
    const int bid   = blockIdx.x;
    const int zseg  = bid & 3;
    const int strip = (bid >> 2) & 15;
    const int b     = bid >> 6;
    const int tid   = threadIdx.x;
    const int lane  = tid & 31;
    const int wid   = tid >> 5;

    const float4* __restrict__ p =
        reinterpret_cast<const float4*>(pred) + (long long)b * (PLANE4 * 128);
    const int  o    = strip * 256 + tid;   // float4 index within a plane
    const int  grow = o >> 5;              // global row (lane == col4)
    const bool do_h = (grow < 127);
    const bool do_w = (lane != 31);
    const int  z0   = zseg * ZLEN;

    int   ci = 0, ch = 0;                  // exact integer counts (alu pipe)
    float mx = 0.f, sds = 0.f, s1 = 0.f, s2 = 0.f;

    // Seed prev with plane z0-1 (z0==0: self-diff contributes 0).
    const int zp = (z0 > 0) ? (z0 - 1) : 0;
    float4 prev = p[zp * PLANE4 + o];

    const float4* pv = p + (long long)z0 * PLANE4 + o;
    const float4* ph = pv + 32;

#pragma unroll 4
    for (int i = 0; i < ZLEN; ++i) {
        const float4 v = pv[i * PLANE4];
        float4 h;
        if (do_h) h = ph[i * PLANE4];

        // w-direction: intra-vector diffs + cross-vector via shuffle.
        const float nx = __shfl_down_sync(0xffffffffu, v.x, 1);
        float g = fabsf(v.y - v.x) + fabsf(v.z - v.y) + fabsf(v.w - v.z);
        if (do_w) g += fabsf(nx - v.w);

        // h-direction: row+1 (loaded as v by a sibling warp -> L1 hit).
        if (do_h) {
            g += fabsf(h.x - v.x) + fabsf(h.y - v.y) +
                 fabsf(h.z - v.z) + fabsf(h.w - v.w);
        }
        // d-direction: prev slice held in registers.
        g += fabsf(v.x - prev.x) + fabsf(v.y - prev.y) +
             fabsf(v.z - prev.z) + fabsf(v.w - prev.w);
        prev = v;
        sds += g;

        // thresholds via integer compares (inputs are non-negative).
        const float xs[4] = {v.x, v.y, v.z, v.w};
#pragma unroll
        for (int k = 0; k < 4; ++k) {
            const float    x  = xs[k];
            const unsigned xu = __float_as_uint(x);
            if (xu > U01) {                // x > 0.01f
                ci++;
                s1 += x;
                s2  = fmaf(x, x, s2);
            }
            if (xu > U05) ch++;            // x > 0.5f
            mx = fmaxf(mx, x);
        }
    }

    // ---- block reduction (8 warps) ----
    float acc[NACC] = {(float)ci, (float)ch, mx, sds, s1, s2};
#pragma unroll
    for (int k = 0; k < NACC; ++k) {
#pragma unroll
        for (int off = 16; off; off >>= 1) {
            const float t = __shfl_xor_sync(0xffffffffu, acc[k], off);
            acc[k] = (k == 2) ? fmaxf(acc[k], t) : (acc[k] + t);
        }
    }
    __shared__ float red[8][NACC];
    __shared__ float fin[NB][NACC];
    __shared__ float lsh[NB];
    __shared__ unsigned int tick_sh;
    if (lane == 0) {
#pragma unroll
        for (int k = 0; k < NACC; ++k) red[wid][k] = acc[k];
    }
    __syncthreads();

    if (tid == 0) {
#pragma unroll
        for (int k = 0; k < NACC; ++k) {
            float r = red[0][k];
#pragma unroll
            for (int w = 1; w < 8; ++w)
                r = (k == 2) ? fmaxf(r, red[w][k]) : (r + red[w][k]);
            g_part[bid * NACC + k] = r;
        }
        __threadfence();
        tick_sh = atomicAdd(&g_ticket, 1u);
    }
    __syncthreads();
    if (tick_sh != (unsigned)(NBLK - 1)) return;

    // ---- last block: deterministic fixed-order final reduction ----
    __threadfence();  // acquire other blocks' g_part writes

    constexpr int PER_B = STRIPS * ZSEGS;  // 64 partials per batch
    if (tid < NB * NACC) {
        const int fb = tid / NACC;
        const int fk = tid % NACC;
        const float* base = &g_part[(fb * PER_B) * NACC + fk];
        float r = base[0];
#pragma unroll
        for (int c = 1; c < PER_B; ++c) {
            const float t = base[c * NACC];
            r = (fk == 2) ? fmaxf(r, t) : (r + t);
        }
        fin[fb][fk] = r;
    }
    __syncthreads();

    if (tid < NB) {
        const float cnt   = fin[tid][0];
        const float chigh = fin[tid][1];
        const float mxv   = fin[tid][2];
        const float sg    = fin[tid][3];
        const float S1    = fin[tid][4];
        const float S2    = fin[tid][5];

        const float invN   = 1.f / 2097152.f;        // 1/128^3
        const float invND3 = 1.f / 6242304.f;        // 1/(3*127*128*128)

        const float act = cnt * invN;
        float loss = fmaxf(0.005f - act, 0.f) * 15.f;

        const float high = chigh * invN;
        loss += fmaxf(high - 0.03f, 0.f) * 5.f;

        const float avg_grad = sg * invND3;
        if (mxv > 0.3f) loss += fminf(avg_grad, 1.f) * 5.f;

        const float cnt_safe = fmaxf(cnt, 1.f);
        const float m  = S1 / cnt_safe;
        const float sq = fmaxf(S2 - 2.f * m * S1 + m * m * cnt, 0.f);
        const bool gate = (act > 0.001f) && (cnt > 1.f);
        const float var = gate ? (sq / fmaxf(cnt - 1.f, 1.f)) : 1.f;
        const float rel_std = sqrtf(var) / (m + 1e-6f);
        const float pen = expf(-5.f * rel_std);
        loss += (gate ? pen : 0.f) * 7.f;

        lsh[tid] = loss;
    }
    __syncthreads();
    if (tid == 0) {
        float t = 0.f;
#pragma unroll
        for (int i = 0; i < NB; ++i) t += lsh[i];
        out[0] = t * (1.f / 16.f);
        g_ticket = 0;  // reset for next (graph-replayed) launch
    }
}

extern "C" void kernel_launch(void* const* d_in, const int* in_sizes, int n_in,
                              void* d_out, int out_size) {
    (void)in_sizes; (void)n_in; (void)out_size;
    const float* pred = (const float*)d_in[0];
    float* out = (float*)d_out;
    lesion_fused<<<NBLK, THREADS>>>(pred, out);
}